// round 14
// baseline (speedup 1.0000x reference)
#include <cuda_runtime.h>
#include <math.h>

#define NQ 14
#define NL 4
#define NG 56
#define NC 10
#define BATCH 1024
#define CHALF 8192          // per-w C table: 64 (inner, folded) x 128 (outer)
#define BT 128              // samples per block

#define HD __host__ __device__

// =============== constexpr GF(2) circuit tables (frame validated R4-R13) ===============
struct Mat { unsigned c[NQ]; };
HD constexpr unsigned permP(unsigned a) {
    unsigned t = a ^ (a >> 1);
    t ^= t >> 2; t ^= t >> 4; t ^= t >> 8;
    return (t & 0x1FFFu) | (((t ^ (a >> 13)) & 1u) << 13);
}
HD constexpr Mat buildP() { Mat m{}; for (int k = 0; k < NQ; k++) m.c[k] = permP(1u << k); return m; }
HD constexpr unsigned mapv(const Mat& m, unsigned a) {
    unsigned r = 0; for (int k = 0; k < NQ; k++) if ((a >> k) & 1u) r ^= m.c[k]; return r;
}
HD constexpr Mat mmul(const Mat& A, const Mat& B) {
    Mat C{}; for (int k = 0; k < NQ; k++) C.c[k] = mapv(A, B.c[k]); return C;
}
HD constexpr Mat minv(Mat a) {
    Mat e{}; for (int i = 0; i < NQ; i++) e.c[i] = 1u << i;
    for (int r = 0; r < NQ; r++) {
        int p = r; while (!((a.c[p] >> r) & 1u)) ++p;
        unsigned t = a.c[r]; a.c[r] = a.c[p]; a.c[p] = t;
        t = e.c[r]; e.c[r] = e.c[p]; e.c[p] = t;
        for (int q = 0; q < NQ; q++)
            if (q != r && ((a.c[q] >> r) & 1u)) { a.c[q] ^= a.c[r]; e.c[q] ^= e.c[r]; }
    }
    return e;
}
HD constexpr Mat pinvPow(int l) {
    Mat r{}; for (int i = 0; i < NQ; i++) r.c[i] = 1u << i;
    Mat pi = minv(buildP());
    for (int i = 0; i < l; i++) r = mmul(pi, r);
    return r;
}
HD constexpr unsigned lmask(int l, int w) { return mapv(pinvPow(l), 1u << (13 - w)); }
HD constexpr unsigned rowm(const Mat& m, int bit) {
    unsigned r = 0; for (int k = 0; k < NQ; k++) r |= ((m.c[k] >> bit) & 1u) << k; return r;
}
HD constexpr int par14(unsigned x) { int p = 0; for (int i = 0; i < NQ; i++) p ^= (x >> i) & 1u; return p; }
HD constexpr int topbit(unsigned x) { int t = -1; for (int i = 0; i < NQ; i++) if ((x >> i) & 1u) t = i; return t; }

struct Circ {
    unsigned mg[NG];
    unsigned long long ac[NQ];
};
struct FoldC {
    int fl[NQ];                 // 1: fold on low half (inner=LO bits 0-6), 0: fold high
    int it[NQ];                 // inner fold top bit (removed from inner index)
    unsigned im[NQ];            // inner fold XOR mask
    unsigned om[NQ];            // outer fold XOR mask
};
HD constexpr Circ makeCirc() {
    Circ c{};
    for (int l = 0; l < NL; l++)
        for (int w = 0; w < NQ; w++) c.mg[l * NQ + w] = lmask(l, w);
    Mat p = buildP(); Mat p2 = mmul(p, p); Mat p4 = mmul(p2, p2);
    for (int w = 0; w < NQ; w++) {
        unsigned rw = rowm(p4, 13 - w);
        unsigned long long m = 0;
        for (int g = 0; g < NG; g++)
            if (par14(c.mg[g] & rw)) m |= 1ull << g;
        c.ac[w] = m;
    }
    return c;
}
HD constexpr FoldC makeFold() {
    FoldC f{};
    Mat p = buildP(); Mat p2 = mmul(p, p); Mat p4 = mmul(p2, p2);
    for (int w = 0; w < NQ; w++) {
        unsigned rw = rowm(p4, 13 - w);
        unsigned rl = rw & 127u, rh = rw >> 7;
        if (rl) { f.fl[w] = 1; f.it[w] = topbit(rl); f.im[w] = rl; f.om[w] = rh; }
        else    { f.fl[w] = 0; f.it[w] = topbit(rh); f.im[w] = rh; f.om[w] = 0;  }
    }
    return f;
}
// per-w gate lists SORTED BY 4-bit outer class, with prefix offsets: makes the
// WHT bucket index a compile-time constant (register S[k]) with runtime bounds.
struct PrepT {
    int ofs[NQ][17];
    unsigned gmask[NQ][NG];     // mask with the 4 class bits cleared
    int gidx[NQ][NG];           // theta index
};
HD constexpr PrepT makePrep() {
    PrepT p{};
    Circ c = makeCirc();
    FoldC f = makeFold();
    for (int w = 0; w < NQ; w++) {
        int sh = f.fl[w] ? 7 : 0;
        int n = 0;
        p.ofs[w][0] = 0;
        for (int cl = 0; cl < 16; cl++) {
            for (int g = 0; g < NG; g++) if ((c.ac[w] >> g) & 1ull) {
                unsigned m = c.mg[g];
                if ((int)((m >> sh) & 0xFu) == cl) {
                    p.gmask[w][n] = m & ~(0xFu << sh);
                    p.gidx[w][n]  = g;
                    n++;
                }
            }
            p.ofs[w][cl + 1] = n;
        }
    }
    return p;
}

__constant__ PrepT dP = makePrep();
__constant__ FoldC dF = makeFold();

// =============== static scratch ===============
__device__ float gZt[NQ * BATCH];     // <Z_w>, transposed [w][b]

__device__ __forceinline__ unsigned depbit(unsigned i, int t) {
    return ((i >> t) << (t + 1)) | (i & ((1u << t) - 1u));
}
// product over 7 wires (base-q), selecting f1/f0 by bit q of v
__device__ __forceinline__ float prod7(const float* __restrict__ f0b,
                                       const float* __restrict__ f1b,
                                       unsigned v, int base) {
    float p = 1.f;
    #pragma unroll
    for (int q = 0; q < 7; q++)
        p *= ((v >> q) & 1) ? f1b[base - q] : f0b[base - q];
    return p;
}

// =============== K1: fully fused — per-block C_w build + tables + contraction =========
// grid (8, 14), 512 threads. Block (bx, w): samples [bx*128, bx*128+128), wire w.
__global__ void __launch_bounds__(512, 1) k_main(const float* __restrict__ qp,
                                                 const float* __restrict__ x) {
    extern __shared__ float sm[];
    float* Cs   = sm;                  // [inner'][outer] 64x128 = 32 KB
    float* INs  = Cs + CHALF;          // [b][inner'] 128x65 (padded)
    float* OUTs = INs + 128 * 65;      // [b][outer]  128x128
    float* f0s  = OUTs + 128 * 128;    // [b][16] sincos tables
    float* f1s  = f0s + 128 * 16;
    __shared__ float th[NG];

    const int w = blockIdx.y, b0 = blockIdx.x * BT, t = threadIdx.x;
    const int fl = dF.fl[w], tt = dF.it[w];
    const unsigned im = dF.im[w], om = dF.om[w];

    // ---- stage A: theta + per-sample (f0,f1) wire factors ----
    if (t < NG) th[t] = qp[t];
    #pragma unroll
    for (int k = 0; k < 4; k++) {
        int idx = t + 512 * k;                 // 128 samples x 14 wires = 1792
        if (idx < BT * NQ) {
            int b = idx / NQ, q = idx - b * NQ;
            float sn, c;
            __sincosf(0.5f * x[(b0 + b) * NQ + q], &sn, &c);
            const float r = 0.70710678118654752440f;   // chi = H (cos, sin)
            f0s[b * 16 + q] = (c + sn) * r;
            f1s[b * 16 + q] = (c - sn) * r;
        }
    }
    __syncthreads();

    // ---- stage B1: C_w tile via class-bucketed WHT-16 (one slot per thread) ----
    {
        const int ip = t >> 3, oh = t & 7;     // inner'(64) x outer-high(8)
        const unsigned inner = depbit((unsigned)ip, tt);
        const unsigned arest = fl ? (((unsigned)oh << 11) | inner)
                                  : ((inner << 7) | ((unsigned)oh << 4));
        float S[16];
        #pragma unroll
        for (int k = 0; k < 16; k++) {
            float s = 0.f;
            const int e = dP.ofs[w][k + 1];
            for (int i = dP.ofs[w][k]; i < e; i++) {
                float v = th[dP.gidx[w][i]];
                s += (__popc(arest & dP.gmask[w][i]) & 1) ? -v : v;
            }
            S[k] = s;
        }
        #pragma unroll
        for (int stp = 1; stp < 16; stp <<= 1) {
            #pragma unroll
            for (int j = 0; j < 16; j++)
                if (!(j & stp)) { float u = S[j], v = S[j | stp]; S[j] = u + v; S[j | stp] = u - v; }
        }
        float4* dst = (float4*)(Cs + ip * 128 + oh * 16);
        #pragma unroll
        for (int q = 0; q < 4; q++)
            dst[q] = make_float4(__cosf(S[4 * q]), __cosf(S[4 * q + 1]),
                                 __cosf(S[4 * q + 2]), __cosf(S[4 * q + 3]));
    }

    // ---- stage B2: IN/OUT tables from (f0,f1) ----
    const int ibase = fl ? 13 : 6, obase = fl ? 6 : 13;
    #pragma unroll
    for (int k = 0; k < 16; k++) {             // IN: 128x64, folded half, x2 weight
        int i = t + 512 * k;
        int b = i >> 6, ii = i & 63;
        unsigned vi = depbit((unsigned)ii, tt);
        const float* f0b = f0s + b * 16;
        const float* f1b = f1s + b * 16;
        INs[b * 65 + ii] = 2.f * prod7(f0b, f1b, vi, ibase) * prod7(f0b, f1b, vi ^ im, ibase);
    }
    #pragma unroll
    for (int k = 0; k < 32; k++) {             // OUT: 128x128
        int i = t + 512 * k;
        int b = i >> 7, o = i & 127;
        const float* f0b = f0s + b * 16;
        const float* f1b = f1s + b * 16;
        OUTs[b * 128 + o] = prod7(f0b, f1b, (unsigned)o, obase) *
                            prod7(f0b, f1b, (unsigned)o ^ om, obase);
    }
    __syncthreads();

    // ---- stage C: contraction Z[w,b] = OUT^T C IN ----
    const int ug = t & 15;                     // outer block: 8 consecutive floats at 8*ug
    const int bg = t >> 4;                     // sample group: b = bg*4 + j
    unsigned long long acc[4][4];
    #pragma unroll
    for (int j = 0; j < 4; j++)
        #pragma unroll
        for (int i = 0; i < 4; i++) acc[j][i] = 0ull;

    for (int v = 0; v < 64; v++) {
        ulonglong2 p0 = *(const ulonglong2*)(Cs + v * 128 + 8 * ug);
        ulonglong2 p1 = *(const ulonglong2*)(Cs + v * 128 + 8 * ug + 4);
        unsigned long long cc[4] = { p0.x, p0.y, p1.x, p1.y };
        #pragma unroll
        for (int j = 0; j < 4; j++) {
            float ll = INs[(bg * 4 + j) * 65 + v];
            unsigned long long llp;
            asm("mov.b64 %0, {%1, %1};" : "=l"(llp) : "f"(ll));
            #pragma unroll
            for (int i = 0; i < 4; i++)
                asm("fma.rn.f32x2 %0, %1, %2, %3;"
                    : "=l"(acc[j][i]) : "l"(cc[i]), "l"(llp), "l"(acc[j][i]));
        }
    }

    #pragma unroll
    for (int j = 0; j < 4; j++) {
        float s = 0.f;
        const float* hh = OUTs + (bg * 4 + j) * 128 + 8 * ug;
        #pragma unroll
        for (int i = 0; i < 4; i++) {
            float ylo, yhi;
            asm("mov.b64 {%0, %1}, %2;" : "=f"(ylo), "=f"(yhi) : "l"(acc[j][i]));
            s = fmaf(ylo, hh[2 * i], fmaf(yhi, hh[2 * i + 1], s));
        }
        #pragma unroll
        for (int o = 1; o < 16; o <<= 1)
            s += __shfl_xor_sync(0xFFFFFFFFu, s, o);
        if (ug == 0) gZt[w * BATCH + b0 + bg * 4 + j] = s;
    }
}

// =============== K2: logits = Z @ fc_w^T + fc_b (coalesced) ===============
__global__ void k_head(const float* __restrict__ fcw, const float* __restrict__ fcb,
                       float* __restrict__ out) {
    const int b = blockIdx.x * 128 + threadIdx.x;
    float z[NQ];
    #pragma unroll
    for (int w = 0; w < NQ; w++) z[w] = gZt[w * BATCH + b];
    #pragma unroll
    for (int c = 0; c < NC; c++) {
        float s = fcb[c];
        #pragma unroll
        for (int w = 0; w < NQ; w++) s = fmaf(z[w], fcw[c * NQ + w], s);
        out[b * NC + c] = s;
    }
}

extern "C" void kernel_launch(void* const* d_in, const int* in_sizes, int n_in,
                              void* d_out, int out_size) {
    const float* x   = (const float*)d_in[0];   // [1024,14]
    const float* qp  = (const float*)d_in[1];   // [4,14] row-major == gate index g
    const float* fcw = (const float*)d_in[2];   // [10,14]
    const float* fcb = (const float*)d_in[3];   // [10]
    float* out = (float*)d_out;                 // [1024,10]

    const int smK = (CHALF + 128 * 65 + 128 * 128 + 2 * 128 * 16) * (int)sizeof(float); // ~160 KB
    cudaFuncSetAttribute(k_main, cudaFuncAttributeMaxDynamicSharedMemorySize, smK);

    k_main<<<dim3(BATCH / BT, NQ), 512, smK>>>(qp, x);
    k_head<<<BATCH / 128, 128>>>(fcw, fcb, out);
}

// round 15
// speedup vs baseline: 1.3741x; 1.3741x over previous
#include <cuda_runtime.h>
#include <math.h>

#define NQ 14
#define NL 4
#define NG 56
#define NC 10
#define BATCH 1024
#define CHALF 8192          // per-w C table: 64 (inner, folded) x 128 (outer)
#define BT 128              // samples per contract block

#define HD __host__ __device__

// =============== constexpr GF(2) circuit tables (frame validated R4-R14) ===============
struct Mat { unsigned c[NQ]; };
HD constexpr unsigned permP(unsigned a) {
    unsigned t = a ^ (a >> 1);
    t ^= t >> 2; t ^= t >> 4; t ^= t >> 8;
    return (t & 0x1FFFu) | (((t ^ (a >> 13)) & 1u) << 13);
}
HD constexpr Mat buildP() { Mat m{}; for (int k = 0; k < NQ; k++) m.c[k] = permP(1u << k); return m; }
HD constexpr unsigned mapv(const Mat& m, unsigned a) {
    unsigned r = 0; for (int k = 0; k < NQ; k++) if ((a >> k) & 1u) r ^= m.c[k]; return r;
}
HD constexpr Mat mmul(const Mat& A, const Mat& B) {
    Mat C{}; for (int k = 0; k < NQ; k++) C.c[k] = mapv(A, B.c[k]); return C;
}
HD constexpr Mat minv(Mat a) {
    Mat e{}; for (int i = 0; i < NQ; i++) e.c[i] = 1u << i;
    for (int r = 0; r < NQ; r++) {
        int p = r; while (!((a.c[p] >> r) & 1u)) ++p;
        unsigned t = a.c[r]; a.c[r] = a.c[p]; a.c[p] = t;
        t = e.c[r]; e.c[r] = e.c[p]; e.c[p] = t;
        for (int q = 0; q < NQ; q++)
            if (q != r && ((a.c[q] >> r) & 1u)) { a.c[q] ^= a.c[r]; e.c[q] ^= e.c[r]; }
    }
    return e;
}
HD constexpr Mat pinvPow(int l) {
    Mat r{}; for (int i = 0; i < NQ; i++) r.c[i] = 1u << i;
    Mat pi = minv(buildP());
    for (int i = 0; i < l; i++) r = mmul(pi, r);
    return r;
}
HD constexpr unsigned lmask(int l, int w) { return mapv(pinvPow(l), 1u << (13 - w)); }
HD constexpr unsigned rowm(const Mat& m, int bit) {
    unsigned r = 0; for (int k = 0; k < NQ; k++) r |= ((m.c[k] >> bit) & 1u) << k; return r;
}
HD constexpr int par14(unsigned x) { int p = 0; for (int i = 0; i < NQ; i++) p ^= (x >> i) & 1u; return p; }
HD constexpr int topbit(unsigned x) { int t = -1; for (int i = 0; i < NQ; i++) if ((x >> i) & 1u) t = i; return t; }

struct Circ {
    unsigned mg[NG];
    unsigned long long ac[NQ];
};
struct FoldC {
    int fl[NQ];                 // 1: fold on low half (inner=LO bits 0-6), 0: fold high
    int it[NQ];                 // inner fold top bit (removed from inner index)
    unsigned im[NQ];            // inner fold XOR mask
    unsigned om[NQ];            // outer fold XOR mask
};
HD constexpr Circ makeCirc() {
    Circ c{};
    for (int l = 0; l < NL; l++)
        for (int w = 0; w < NQ; w++) c.mg[l * NQ + w] = lmask(l, w);
    Mat p = buildP(); Mat p2 = mmul(p, p); Mat p4 = mmul(p2, p2);
    for (int w = 0; w < NQ; w++) {
        unsigned rw = rowm(p4, 13 - w);
        unsigned long long m = 0;
        for (int g = 0; g < NG; g++)
            if (par14(c.mg[g] & rw)) m |= 1ull << g;
        c.ac[w] = m;
    }
    return c;
}
HD constexpr FoldC makeFold() {
    FoldC f{};
    Mat p = buildP(); Mat p2 = mmul(p, p); Mat p4 = mmul(p2, p2);
    for (int w = 0; w < NQ; w++) {
        unsigned rw = rowm(p4, 13 - w);
        unsigned rl = rw & 127u, rh = rw >> 7;
        if (rl) { f.fl[w] = 1; f.it[w] = topbit(rl); f.im[w] = rl; f.om[w] = rh; }
        else    { f.fl[w] = 0; f.it[w] = topbit(rh); f.im[w] = rh; f.om[w] = 0;  }
    }
    return f;
}
// per-w gate lists SORTED BY 4-bit outer class, with prefix offsets: bucket
// index is a compile-time constant (register S[k]); only bounds are runtime.
struct PrepT {
    int ofs[NQ][17];
    unsigned gmask[NQ][NG];     // mask with the 4 class bits cleared
    int gidx[NQ][NG];           // theta index
};
HD constexpr PrepT makePrep() {
    PrepT p{};
    Circ c = makeCirc();
    FoldC f = makeFold();
    for (int w = 0; w < NQ; w++) {
        int sh = f.fl[w] ? 7 : 0;
        int n = 0;
        p.ofs[w][0] = 0;
        for (int cl = 0; cl < 16; cl++) {
            for (int g = 0; g < NG; g++) if ((c.ac[w] >> g) & 1ull) {
                unsigned m = c.mg[g];
                if ((int)((m >> sh) & 0xFu) == cl) {
                    p.gmask[w][n] = m & ~(0xFu << sh);
                    p.gidx[w][n]  = g;
                    n++;
                }
            }
            p.ofs[w][cl + 1] = n;
        }
    }
    return p;
}

__constant__ PrepT dP = makePrep();
__constant__ FoldC dF = makeFold();

// =============== static scratch ===============
__device__ float gC[NQ * CHALF];      // folded C tables: [w][inner'(64) * 128 + outer]
__device__ float gHI[BATCH * 128];
__device__ float gLO[BATCH * 128];
__device__ float gZt[NQ * BATCH];     // <Z_w>, transposed [w][b]
__device__ int   gCnt[BATCH / BT];    // per-bx completion counters (reset by k_prep)

__device__ __forceinline__ unsigned depbit(unsigned i, int t) {
    return ((i >> t) << (t + 1)) | (i & ((1u << t) - 1u));
}

// =============== K1: phase tables (28 blocks) + product tables (512 blocks) ============
// Phase: one thread -> 16 outer-consecutive elements via class-sorted register
// buckets + WHT-16 (R14-validated codegen; no smem RMW chain).
__global__ void k_prep(const float* __restrict__ qp, const float* __restrict__ x) {
    __shared__ float th[NG];
    __shared__ float f0[2][NQ], f1[2][NQ];
    const int t = threadIdx.x;

    if (blockIdx.x == 0 && t < BATCH / BT) gCnt[t] = 0;   // reset tail counters

    if (blockIdx.x < 28) {
        if (t < NG) th[t] = qp[t];
        __syncthreads();
        const int w = blockIdx.x >> 1;
        const int slot = ((blockIdx.x & 1) << 8) + t;    // 0..511
        const int ip = slot >> 3, oh = slot & 7;         // inner'(64) x outer-high(8)
        const unsigned inner = depbit((unsigned)ip, dF.it[w]);
        const unsigned arest = dF.fl[w] ? (((unsigned)oh << 11) | inner)
                                        : ((inner << 7) | ((unsigned)oh << 4));
        float S[16];
        #pragma unroll
        for (int k = 0; k < 16; k++) {
            float s = 0.f;
            const int e = dP.ofs[w][k + 1];
            for (int i = dP.ofs[w][k]; i < e; i++) {
                float v = th[dP.gidx[w][i]];
                s += (__popc(arest & dP.gmask[w][i]) & 1) ? -v : v;
            }
            S[k] = s;
        }
        #pragma unroll
        for (int stp = 1; stp < 16; stp <<= 1) {
            #pragma unroll
            for (int j = 0; j < 16; j++)
                if (!(j & stp)) { float u = S[j], v = S[j | stp]; S[j] = u + v; S[j | stp] = u - v; }
        }
        float4* dst = (float4*)(gC + w * CHALF + ip * 128 + oh * 16);
        #pragma unroll
        for (int q = 0; q < 4; q++)
            dst[q] = make_float4(__cosf(S[4 * q]), __cosf(S[4 * q + 1]),
                                 __cosf(S[4 * q + 2]), __cosf(S[4 * q + 3]));
    } else {
        const int s = t >> 7, tl = t & 127;
        const int b = (blockIdx.x - 28) * 2 + s;
        if (tl < NQ) {
            float sn, c;
            __sincosf(0.5f * x[b * NQ + tl], &sn, &c);
            const float r = 0.70710678118654752440f;    // chi = H (cos, sin)
            f0[s][tl] = (c + sn) * r;
            f1[s][tl] = (c - sn) * r;
        }
        __syncthreads();
        float phi = 1.f, plo = 1.f;
        #pragma unroll
        for (int q = 0; q < 7; q++) {
            phi *= ((tl >> q) & 1) ? f1[s][6 - q]  : f0[s][6 - q];
            plo *= ((tl >> q) & 1) ? f1[s][13 - q] : f0[s][13 - q];
        }
        gHI[b * 128 + tl] = phi;
        gLO[b * 128 + tl] = plo;
    }
}

// =============== K2: contraction Z[w,b] = 2*OUT^T C IN, + fused head tail =============
__global__ void __launch_bounds__(512, 1) k_contract(const float* __restrict__ fcw,
                                                     const float* __restrict__ fcb,
                                                     float* __restrict__ out) {
    extern __shared__ float sm[];
    float* Cs   = sm;                  // [inner'][outer] 64x128 = 32 KB
    float* INs  = Cs + CHALF;          // [b][inner'] 128x65 (padded)
    float* OUTs = INs + 128 * 65;      // [b][outer]  128x128
    __shared__ int lastFlag;
    const int w = blockIdx.y, b0 = blockIdx.x * BT, t = threadIdx.x;
    const int fl = dF.fl[w], tt = dF.it[w];
    const unsigned im = dF.im[w], om = dF.om[w];
    const float* innerSrc = fl ? gLO : gHI;
    const float* outerSrc = fl ? gHI : gLO;

    {   // C copy (coalesced float4)
        const float4* src = (const float4*)(gC + w * CHALF);
        float4* dst = (float4*)Cs;
        #pragma unroll
        for (int i = 0; i < 4; i++) dst[t + 512 * i] = src[t + 512 * i];
    }
    #pragma unroll
    for (int k = 0; k < 16; k++) {     // IN table: folded half, x2 weight
        int i = t + 512 * k;
        int b = i >> 6, ii = i & 63;
        unsigned vi = depbit((unsigned)ii, tt);
        const float* s2 = innerSrc + (b0 + b) * 128;
        INs[b * 65 + ii] = 2.f * s2[vi] * s2[vi ^ im];
    }
    #pragma unroll
    for (int k = 0; k < 32; k++) {     // OUT table: full 128
        int i = t + 512 * k;
        int b = i >> 7, o = i & 127;
        const float* s2 = outerSrc + (b0 + b) * 128;
        OUTs[b * 128 + o] = s2[o] * s2[o ^ om];
    }
    __syncthreads();

    const int ug = t & 15;             // outer block: 8 consecutive floats at 8*ug
    const int bg = t >> 4;             // sample group: b = bg*4 + j
    unsigned long long acc[4][4];
    #pragma unroll
    for (int j = 0; j < 4; j++)
        #pragma unroll
        for (int i = 0; i < 4; i++) acc[j][i] = 0ull;

    for (int v = 0; v < 64; v++) {
        ulonglong2 p0 = *(const ulonglong2*)(Cs + v * 128 + 8 * ug);
        ulonglong2 p1 = *(const ulonglong2*)(Cs + v * 128 + 8 * ug + 4);
        unsigned long long cc[4] = { p0.x, p0.y, p1.x, p1.y };
        #pragma unroll
        for (int j = 0; j < 4; j++) {
            float ll = INs[(bg * 4 + j) * 65 + v];
            unsigned long long llp;
            asm("mov.b64 %0, {%1, %1};" : "=l"(llp) : "f"(ll));
            #pragma unroll
            for (int i = 0; i < 4; i++)
                asm("fma.rn.f32x2 %0, %1, %2, %3;"
                    : "=l"(acc[j][i]) : "l"(cc[i]), "l"(llp), "l"(acc[j][i]));
        }
    }

    #pragma unroll
    for (int j = 0; j < 4; j++) {
        float s = 0.f;
        const float* hh = OUTs + (bg * 4 + j) * 128 + 8 * ug;
        #pragma unroll
        for (int i = 0; i < 4; i++) {
            float ylo, yhi;
            asm("mov.b64 {%0, %1}, %2;" : "=f"(ylo), "=f"(yhi) : "l"(acc[j][i]));
            s = fmaf(ylo, hh[2 * i], fmaf(yhi, hh[2 * i + 1], s));
        }
        #pragma unroll
        for (int o = 1; o < 16; o <<= 1)
            s += __shfl_xor_sync(0xFFFFFFFFu, s, o);
        if (ug == 0) gZt[w * BATCH + b0 + bg * 4 + j] = s;
    }

    // ---- fused head tail: the 14th finishing block for this bx does the head ----
    // Output values are order-independent -> deterministic.
    __syncthreads();
    if (t == 0) {
        __threadfence();                               // publish gZt writes
        int prev = atomicAdd(&gCnt[blockIdx.x], 1);
        lastFlag = (prev == NQ - 1);
    }
    __syncthreads();
    if (lastFlag) {
        __threadfence();                               // acquire other blocks' gZt
        if (t < BT) {
            const int b = b0 + t;
            float z[NQ];
            #pragma unroll
            for (int q = 0; q < NQ; q++) z[q] = gZt[q * BATCH + b];
            #pragma unroll
            for (int c = 0; c < NC; c++) {
                float s = fcb[c];
                #pragma unroll
                for (int q = 0; q < NQ; q++) s = fmaf(z[q], fcw[c * NQ + q], s);
                out[b * NC + c] = s;
            }
        }
    }
}

extern "C" void kernel_launch(void* const* d_in, const int* in_sizes, int n_in,
                              void* d_out, int out_size) {
    const float* x   = (const float*)d_in[0];   // [1024,14]
    const float* qp  = (const float*)d_in[1];   // [4,14] row-major == gate index g
    const float* fcw = (const float*)d_in[2];   // [10,14]
    const float* fcb = (const float*)d_in[3];   // [10]
    float* out = (float*)d_out;                 // [1024,10]

    const int smK = (CHALF + 128 * 65 + 128 * 128) * (int)sizeof(float);  // ~129 KB
    cudaFuncSetAttribute(k_contract, cudaFuncAttributeMaxDynamicSharedMemorySize, smK);

    k_prep<<<540, 256>>>(qp, x);
    k_contract<<<dim3(BATCH / BT, NQ), 512, smK>>>(fcw, fcb, out);
}